// round 15
// baseline (speedup 1.0000x reference)
#include <cuda_runtime.h>
#include <math.h>

#define Nn 50000
#define Ee 800000
#define Ff 64
#define Tt 3
#define NSs 64
#define NTOT (4*Nn)
#define SCAN_TILE 4096
#define SCAN_BLOCKS ((Nn + SCAN_TILE - 1) / SCAN_TILE)   // 13

// ---------------- scratch (device globals; no allocation allowed) ----------------
__device__ __align__(16) float g_diff[Nn*192];   // per node: 3 normalized-difference rows
__device__ unsigned char g_mask[Ee];
__device__ unsigned long long g_pack[Nn];         // c1|c2<<16|c3<<32|deg<<48
__device__ int g_off[Nn+1];
__device__ int g_fill[Nn];
__device__ int g_eid[Ee];                         // packed: src | (mask<<16)
__device__ int g_bsum[SCAN_BLOCKS];
__device__ int g_scancnt;
__device__ float g_dinv[4*Nn];
__device__ __align__(16) float g_h1[NTOT*Ff];
__device__ __align__(16) float g_x2[Nn*Ff];       // replica-0 rows only
__device__ int g_cls[NTOT];
__device__ __align__(16) float g_hyper[NSs*Ff];
__device__ float g_colsum[NSs];

// ---------------- register-blocked GEMM (diff rows + global init) ----------------
__global__ __launch_bounds__(128)
void gemm_rb(const float* __restrict__ X, const float* __restrict__ W,
             const float* __restrict__ bias, int rows)
{
    __shared__ float As[128*64];   // 32KB
    __shared__ float Bs[64*64];    // 16KB
    const int tid = threadIdx.x;
    const int tx = tid & 7;
    const int ty = tid >> 3;
    const int b  = blockIdx.y;
    const int row0 = blockIdx.x * 128;

    if (b == 0) {
        int gi = blockIdx.x * 128 + tid;
        if (gi < Nn) { g_pack[gi] = 0ULL; g_fill[gi] = 0; }
        if (blockIdx.x == 0) {
            for (int i = tid; i < NSs*Ff; i += 128) g_hyper[i] = 0.0f;
            if (tid < NSs) g_colsum[tid] = (float)Nn;
            if (tid == 0) g_scancnt = 0;
        }
    }

    const float* Wb = W + (size_t)b * 4096;

#pragma unroll
    for (int it = 0; it < 16; it++) {
        int idx = tid + it * 128;
        int r = idx >> 4, c4 = (idx & 15) << 2;
        int gr = row0 + r;
        float4 v = make_float4(0.f, 0.f, 0.f, 0.f);
        if (gr < rows) v = *(const float4*)&X[(size_t)gr*64 + c4];
        *(float4*)&As[r*64 + c4] = v;
    }
#pragma unroll
    for (int it = 0; it < 8; it++) {
        int idx = tid + it * 128;
        int k = idx >> 4, c4 = (idx & 15) << 2;
        *(float4*)&Bs[k*64 + c4] = *(const float4*)&Wb[k*64 + c4];
    }
    __syncthreads();

    float acc[8][8];
#pragma unroll
    for (int i = 0; i < 8; i++)
#pragma unroll
        for (int j = 0; j < 8; j++) acc[i][j] = 0.f;

    const int rbase = ty * 8;
    const int c0 = tx * 8;
#pragma unroll
    for (int k0 = 0; k0 < 64; k0 += 4) {
        float4 a[8];
#pragma unroll
        for (int i = 0; i < 8; i++) a[i] = *(const float4*)&As[(rbase+i)*64 + k0];
#pragma unroll
        for (int kk = 0; kk < 4; kk++) {
            float4 b0 = *(const float4*)&Bs[(k0+kk)*64 + c0];
            float4 b1 = *(const float4*)&Bs[(k0+kk)*64 + c0 + 4];
            float bb[8] = {b0.x,b0.y,b0.z,b0.w,b1.x,b1.y,b1.z,b1.w};
#pragma unroll
            for (int i = 0; i < 8; i++) {
                float av = (kk==0) ? a[i].x : (kk==1) ? a[i].y : (kk==2) ? a[i].z : a[i].w;
#pragma unroll
                for (int j = 0; j < 8; j++) acc[i][j] += av * bb[j];
            }
        }
    }

    float bj[8];
#pragma unroll
    for (int j = 0; j < 8; j++) bj[j] = bias[(size_t)b*64 + c0 + j];

#pragma unroll
    for (int i = 0; i < 8; i++) {
        int gr = row0 + rbase + i;
        float v[8], x[8];
        float sqv = 0.f, sqx = 0.f;
#pragma unroll
        for (int j = 0; j < 8; j++) {
            v[j] = acc[i][j] + bj[j];
            x[j] = As[(rbase+i)*64 + c0 + j];
            sqv += v[j]*v[j];
            sqx += x[j]*x[j];
        }
        sqv += __shfl_xor_sync(0xffffffffu, sqv, 1);
        sqv += __shfl_xor_sync(0xffffffffu, sqv, 2);
        sqv += __shfl_xor_sync(0xffffffffu, sqv, 4);
        sqx += __shfl_xor_sync(0xffffffffu, sqx, 1);
        sqx += __shfl_xor_sync(0xffffffffu, sqx, 2);
        sqx += __shfl_xor_sync(0xffffffffu, sqx, 4);
        float itn = 1.0f / fmaxf(sqrtf(sqv), 1e-8f);
        float ixn = 1.0f / fmaxf(sqrtf(sqx), 1e-8f);
        if (gr < rows) {
            float d[8];
#pragma unroll
            for (int j = 0; j < 8; j++) d[j] = v[j]*itn - x[j]*ixn;
            float* dst = &g_diff[(size_t)gr*192 + b*64 + c0];
            *(float4*)&dst[0] = make_float4(d[0],d[1],d[2],d[3]);
            *(float4*)&dst[4] = make_float4(d[4],d[5],d[6],d[7]);
        }
    }
}

// ---------------- per-edge masks; 8 lanes per edge ----------------
__global__ void edge_kernel(const int* __restrict__ ei, const float* __restrict__ feat)
{
    int gid = blockIdx.x * blockDim.x + threadIdx.x;
    int e = gid >> 3;
    int q = threadIdx.x & 7;
    if (e >= Ee) return;
    int s = ei[e], d = ei[Ee + e];

    const float4* dp = (const float4*)(g_diff + (size_t)s*192);
    const float4* fp = (const float4*)(feat + (size_t)d*64);
    float4 f0 = fp[q],       f1 = fp[q + 8];
    float4 a0 = dp[q],       a1 = dp[q + 8];
    float4 b0 = dp[16 + q],  b1 = dp[24 + q];
    float4 c0 = dp[32 + q],  c1 = dp[40 + q];

    float p0 = a0.x*f0.x + a0.y*f0.y + a0.z*f0.z + a0.w*f0.w
             + a1.x*f1.x + a1.y*f1.y + a1.z*f1.z + a1.w*f1.w;
    float p1 = b0.x*f0.x + b0.y*f0.y + b0.z*f0.z + b0.w*f0.w
             + b1.x*f1.x + b1.y*f1.y + b1.z*f1.z + b1.w*f1.w;
    float p2 = c0.x*f0.x + c0.y*f0.y + c0.z*f0.z + c0.w*f0.w
             + c1.x*f1.x + c1.y*f1.y + c1.z*f1.z + c1.w*f1.w;
#pragma unroll
    for (int o = 4; o; o >>= 1) {
        p0 += __shfl_xor_sync(0xffffffffu, p0, o);
        p1 += __shfl_xor_sync(0xffffffffu, p1, o);
        p2 += __shfl_xor_sync(0xffffffffu, p2, o);
    }
    if (q == 0) {
        unsigned m = 0;
        unsigned long long inc = 1ULL << 48;
        if (p0 > 0.f) { m |= 1u; inc += 1ULL; }
        if (p1 > 0.f) { m |= 2u; inc += 1ULL << 16; }
        if (p2 > 0.f) { m |= 4u; inc += 1ULL << 32; }
        g_mask[e] = (unsigned char)m;
        atomicAdd(&g_pack[d], inc);
    }
}

// ---------------- single-pass scan (13 co-resident blocks, spin barrier) + dinv ----------------
__global__ void scanAC_kernel()
{
    __shared__ int wsum[32];
    __shared__ int carry_s;
    int tid = threadIdx.x, lane = tid & 31, wid = tid >> 5;
    int idx4 = blockIdx.x * SCAN_TILE + tid * 4;

    unsigned long long pk0 = 0, pk1 = 0, pk2 = 0, pk3 = 0;
    if (idx4     < Nn) pk0 = g_pack[idx4];
    if (idx4 + 1 < Nn) pk1 = g_pack[idx4+1];
    if (idx4 + 2 < Nn) pk2 = g_pack[idx4+2];
    if (idx4 + 3 < Nn) pk3 = g_pack[idx4+3];
    int v0 = (int)(pk0 >> 48), v1 = (int)(pk1 >> 48);
    int v2 = (int)(pk2 >> 48), v3 = (int)(pk3 >> 48);

    int local = v0 + v1 + v2 + v3;
    int incl = local;
#pragma unroll
    for (int o = 1; o < 32; o <<= 1) {
        int t = __shfl_up_sync(0xffffffffu, incl, o);
        if (lane >= o) incl += t;
    }
    if (lane == 31) wsum[wid] = incl;
    __syncthreads();
    if (wid == 0) {
        int s = wsum[lane];
        int si = s;
#pragma unroll
        for (int o = 1; o < 32; o <<= 1) {
            int t = __shfl_up_sync(0xffffffffu, si, o);
            if (lane >= o) si += t;
        }
        wsum[lane] = si - s;
        if (lane == 31) {
            g_bsum[blockIdx.x] = si;
            __threadfence();
            atomicAdd(&g_scancnt, 1);
        }
    }
    __syncthreads();
    int excl = wsum[wid] + (incl - local);

    if (tid == 0) {
        while (*(volatile int*)&g_scancnt < SCAN_BLOCKS) { }
        __threadfence();
        int c = 0;
        for (int j = 0; j < (int)blockIdx.x; j++) c += *(volatile int*)&g_bsum[j];
        carry_s = c;
        if (blockIdx.x == SCAN_BLOCKS - 1)
            g_off[Nn] = c + *(volatile int*)&g_bsum[SCAN_BLOCKS - 1];
    }
    __syncthreads();
    int carry = carry_s;
    excl += carry;

    if (idx4 + 3 < Nn) {
        *(int4*)&g_off[idx4] = make_int4(excl, excl+v0, excl+v0+v1, excl+v0+v1+v2);
    } else if (idx4 < Nn) {
        g_off[idx4] = excl;
        if (idx4+1 < Nn) g_off[idx4+1] = excl + v0;
        if (idx4+2 < Nn) g_off[idx4+2] = excl + v0 + v1;
    }
#pragma unroll
    for (int j = 0; j < 4; j++) {
        int i = idx4 + j;
        if (i >= Nn) break;
        unsigned long long pk = (j==0) ? pk0 : (j==1) ? pk1 : (j==2) ? pk2 : pk3;
        g_dinv[i]        = rsqrtf((float)(int)(pk >> 48) + 1.0f);
        g_dinv[Nn + i]   = rsqrtf((float)(int)(pk & 0xFFFF) + 2.0f);
        g_dinv[2*Nn + i] = rsqrtf((float)(int)((pk >> 16) & 0xFFFF) + 2.0f);
        g_dinv[3*Nn + i] = rsqrtf((float)(int)((pk >> 32) & 0xFFFF) + 2.0f);
    }
}

// ---------------- CSR fill (packed src|mask) ----------------
__global__ void fill_kernel(const int* __restrict__ ei)
{
    int e = blockIdx.x * blockDim.x + threadIdx.x;
    if (e >= Ee) return;
    int s = ei[e];
    int d = ei[Ee + e];
    unsigned m = g_mask[e];
    int p = g_off[d] + atomicAdd(&g_fill[d], 1);
    g_eid[p] = s | ((int)m << 16);
}

// ---------------- fused GCN layer: gather in input space, multiply by W AFTER aggregation ----------------
// FUSE=0: SRC=feat (relu applied on the fly), out = relu(z@W + b) for all 4 replicas -> g_h1.
// FUSE=1: SRC=g_h1, x2 = z@W + b; replica-0 x2 stored; logits=relu(x2)@LW + Lb; argmax -> g_cls.
template<int FUSE>
__global__ __launch_bounds__(256)
void gcn_fused(const float* __restrict__ SRC,
               const float* __restrict__ W, const float* __restrict__ bias,
               float* __restrict__ out,
               const float* __restrict__ LW, const float* __restrict__ Lb)
{
    __shared__ float Wsm[64*68];
    __shared__ float bs[64];
    __shared__ float W2sm[FUSE ? 64*68 : 1];
    __shared__ float b2s[FUSE ? 64 : 1];
    __shared__ float rowsm[8][4][68];
    int tid = threadIdx.x;
    for (int i = tid; i < 4096; i += 256) {
        int k = i >> 6, j = i & 63;
        Wsm[k*68 + j] = W[i];
        if (FUSE) W2sm[k*68 + j] = LW[i];
    }
    if (tid < 64) { bs[tid] = bias[tid]; if (FUSE) b2s[tid] = Lb[tid]; }
    __syncthreads();

    int wid = tid >> 5;
    int lane = tid & 31;
    int h = lane >> 4;
    int q = lane & 15;

    for (int rep = 0; rep < 8; rep++) {
        int i = blockIdx.x * 64 + wid * 8 + rep;
        if (i >= Nn) break;

        float di0 = g_dinv[i];
        float di1 = g_dinv[Nn + i];
        float di2 = g_dinv[2*Nn + i];
        float di3 = g_dinv[3*Nn + i];
        float4 A0 = make_float4(0,0,0,0), A1 = A0, A2 = A0, A3 = A0;
        int beg = g_off[i], end = g_off[i+1];

#define EDGE(kk) { \
        int p = g_eid[kk]; \
        int s = p & 0xFFFF; \
        unsigned m = (unsigned)p >> 16; \
        float ad = g_dinv[s]; \
        float4 r = ((const float4*)(SRC + (size_t)s*Ff))[q]; \
        if (!FUSE) { r.x=fmaxf(r.x,0.f); r.y=fmaxf(r.y,0.f); r.z=fmaxf(r.z,0.f); r.w=fmaxf(r.w,0.f); } \
        float c0 = ad * di0; \
        A0.x += r.x*c0; A0.y += r.y*c0; A0.z += r.z*c0; A0.w += r.w*c0; \
        if (m & 1u) { float c = ad*di1; A1.x += r.x*c; A1.y += r.y*c; A1.z += r.z*c; A1.w += r.w*c; } \
        if (m & 2u) { float c = ad*di2; A2.x += r.x*c; A2.y += r.y*c; A2.z += r.z*c; A2.w += r.w*c; } \
        if (m & 4u) { float c = ad*di3; A3.x += r.x*c; A3.y += r.y*c; A3.z += r.z*c; A3.w += r.w*c; } }

        int k = beg + h;
        for (; k + 2 < end; k += 4) { EDGE(k); EDGE(k + 2); }
        if (k < end) EDGE(k);
#undef EDGE

#define COMB(A) \
        A.x += __shfl_xor_sync(0xffffffffu, A.x, 16); \
        A.y += __shfl_xor_sync(0xffffffffu, A.y, 16); \
        A.z += __shfl_xor_sync(0xffffffffu, A.z, 16); \
        A.w += __shfl_xor_sync(0xffffffffu, A.w, 16);
        COMB(A0) COMB(A1) COMB(A2) COMB(A3)
#undef COMB

        float4 s0 = ((const float4*)(SRC + (size_t)i*Ff))[q];
        if (!FUSE) { s0.x=fmaxf(s0.x,0.f); s0.y=fmaxf(s0.y,0.f); s0.z=fmaxf(s0.z,0.f); s0.w=fmaxf(s0.w,0.f); }

        // aggregated rows in input space (no bias yet)
        float4 zA, zB;
        if (h == 0) {
            float c = di0*di0;
            zA.x = A0.x + s0.x*c; zA.y = A0.y + s0.y*c;
            zA.z = A0.z + s0.z*c; zA.w = A0.w + s0.w*c;
            float car = di0 * di1, cs = di1 * di1;
            float4 sr = FUSE ? ((const float4*)(SRC + ((size_t)Nn + i)*Ff))[q] : s0;
            zB.x = A1.x + s0.x*car + sr.x*cs; zB.y = A1.y + s0.y*car + sr.y*cs;
            zB.z = A1.z + s0.z*car + sr.z*cs; zB.w = A1.w + s0.w*car + sr.w*cs;
        } else {
            float car = di0 * di2, cs = di2 * di2;
            float4 sr = FUSE ? ((const float4*)(SRC + ((size_t)2*Nn + i)*Ff))[q] : s0;
            zA.x = A2.x + s0.x*car + sr.x*cs; zA.y = A2.y + s0.y*car + sr.y*cs;
            zA.z = A2.z + s0.z*car + sr.z*cs; zA.w = A2.w + s0.w*car + sr.w*cs;
            car = di0 * di3; cs = di3 * di3;
            sr = FUSE ? ((const float4*)(SRC + ((size_t)3*Nn + i)*Ff))[q] : s0;
            zB.x = A3.x + s0.x*car + sr.x*cs; zB.y = A3.y + s0.y*car + sr.y*cs;
            zB.z = A3.z + s0.z*car + sr.z*cs; zB.w = A3.w + s0.w*car + sr.w*cs;
        }

        // stage z rows, multiply by W (post-aggregation GEMM)
        *(float4*)&rowsm[wid][2*h + 0][4*q] = zA;
        *(float4*)&rowsm[wid][2*h + 1][4*q] = zB;
        __syncwarp();

        float wA[4], wB[4];
#pragma unroll
        for (int j = 0; j < 4; j++) { wA[j] = bs[4*q + j]; wB[j] = bs[4*q + j]; }
        {
            const float* r0 = rowsm[wid][2*h + 0];
            const float* r1 = rowsm[wid][2*h + 1];
#pragma unroll 8
            for (int kk = 0; kk < 64; kk++) {
                float z0 = r0[kk];
                float z1 = r1[kk];
                float4 w = *(const float4*)&Wsm[kk*68 + 4*q];
                wA[0] += z0*w.x; wA[1] += z0*w.y; wA[2] += z0*w.z; wA[3] += z0*w.w;
                wB[0] += z1*w.x; wB[1] += z1*w.y; wB[2] += z1*w.z; wB[3] += z1*w.w;
            }
        }

        if (!FUSE) {
            // relu + write all 4 replica rows of h1
            float4 oA = make_float4(fmaxf(wA[0],0.f), fmaxf(wA[1],0.f), fmaxf(wA[2],0.f), fmaxf(wA[3],0.f));
            float4 oB = make_float4(fmaxf(wB[0],0.f), fmaxf(wB[1],0.f), fmaxf(wB[2],0.f), fmaxf(wB[3],0.f));
            if (h == 0) {
                ((float4*)(out + (size_t)i*Ff))[q] = oA;
                ((float4*)(out + ((size_t)Nn + i)*Ff))[q] = oB;
            } else {
                ((float4*)(out + ((size_t)2*Nn + i)*Ff))[q] = oA;
                ((float4*)(out + ((size_t)3*Nn + i)*Ff))[q] = oB;
            }
            __syncwarp();
        } else {
            // x2 rows; write replica-0; logits + argmax
            if (h == 0)
                ((float4*)(out + (size_t)i*Ff))[q] = make_float4(wA[0], wA[1], wA[2], wA[3]);
            __syncwarp();
            *(float4*)&rowsm[wid][2*h + 0][4*q] = make_float4(wA[0], wA[1], wA[2], wA[3]);
            *(float4*)&rowsm[wid][2*h + 1][4*q] = make_float4(wB[0], wB[1], wB[2], wB[3]);
            __syncwarp();

            float a0[4], a1[4];
#pragma unroll
            for (int j = 0; j < 4; j++) { a0[j] = b2s[4*q + j]; a1[j] = b2s[4*q + j]; }
            const float* r0 = rowsm[wid][2*h + 0];
            const float* r1 = rowsm[wid][2*h + 1];
#pragma unroll 8
            for (int kk = 0; kk < 64; kk++) {
                float h0 = fmaxf(r0[kk], 0.f);
                float h1 = fmaxf(r1[kk], 0.f);
                float4 w = *(const float4*)&W2sm[kk*68 + 4*q];
                a0[0] += h0*w.x; a0[1] += h0*w.y; a0[2] += h0*w.z; a0[3] += h0*w.w;
                a1[0] += h1*w.x; a1[1] += h1*w.y; a1[2] += h1*w.z; a1[3] += h1*w.w;
            }
            float bv0 = a0[0]; int bi0 = 4*q;
            float bv1 = a1[0]; int bi1 = 4*q;
#pragma unroll
            for (int j = 1; j < 4; j++) {
                if (a0[j] > bv0) { bv0 = a0[j]; bi0 = 4*q + j; }
                if (a1[j] > bv1) { bv1 = a1[j]; bi1 = 4*q + j; }
            }
#pragma unroll
            for (int o = 1; o < 16; o <<= 1) {
                float ov0 = __shfl_xor_sync(0xffffffffu, bv0, o);
                int   oi0 = __shfl_xor_sync(0xffffffffu, bi0, o);
                float ov1 = __shfl_xor_sync(0xffffffffu, bv1, o);
                int   oi1 = __shfl_xor_sync(0xffffffffu, bi1, o);
                if (ov0 > bv0 || (ov0 == bv0 && oi0 < bi0)) { bv0 = ov0; bi0 = oi0; }
                if (ov1 > bv1 || (ov1 == bv1 && oi1 < bi1)) { bv1 = ov1; bi1 = oi1; }
            }
            if (q == 0) {
                g_cls[(size_t)(2*h + 0)*Nn + i] = bi0;
                g_cls[(size_t)(2*h + 1)*Nn + i] = bi1;
            }
            __syncwarp();
        }
    }
}

// ---------------- class aggregation: hyper + softmax column sums ----------------
__global__ void classagg_kernel()
{
    __shared__ float hy[NSs][Ff];
    __shared__ float cs[NSs];
    int tid = threadIdx.x;
    for (int i = tid; i < NSs*Ff; i += 256) (&hy[0][0])[i] = 0.0f;
    if (tid < NSs) cs[tid] = 0.0f;
    __syncthreads();
    int wid = tid >> 5, lane = tid & 31;
    for (int n = blockIdx.x * 8 + wid; n < Nn; n += gridDim.x * 8) {
        int c0 = g_cls[n], c1 = g_cls[Nn + n], c2 = g_cls[2*Nn + n], c3 = g_cls[3*Nn + n];
        float2 x = ((const float2*)(g_x2 + (size_t)n*64))[lane];
#define PROC(c, cnt) { \
        atomicAdd(&hy[(c)][2*lane], x.x); atomicAdd(&hy[(c)][2*lane+1], x.y); \
        if (lane == 0) atomicAdd(&cs[(c)], expf((float)(cnt)) - 1.0f); }
        { int cnt = 1 + (c1==c0) + (c2==c0) + (c3==c0); PROC(c0, cnt); }
        if (c1 != c0)                         { int cnt = 1 + (c2==c1) + (c3==c1); PROC(c1, cnt); }
        if (c2 != c0 && c2 != c1)             { int cnt = 1 + (c3==c2);            PROC(c2, cnt); }
        if (c3 != c0 && c3 != c1 && c3 != c2) {                                    PROC(c3, 1);   }
#undef PROC
    }
    __syncthreads();
    for (int i = tid; i < NSs*Ff; i += 256) atomicAdd(&g_hyper[i], (&hy[0][0])[i]);
    if (tid < NSs) atomicAdd(&g_colsum[tid], cs[tid]);
}

// ---------------- fused outputs: H_soft + hyper copy + dots; 8 nodes/warp ----------------
__global__ __launch_bounds__(256)
void outputs_kernel(const float* __restrict__ feat,
                    float* __restrict__ outHs, float* __restrict__ outHy,
                    float* __restrict__ outD)
{
    __shared__ __align__(16) float hyT[64][68];
    __shared__ float inv[NSs];
    __shared__ __align__(16) float frow[8][64];
    int tid = threadIdx.x;
    for (int i = tid; i < 4096; i += 256) hyT[i >> 6][i & 63] = g_hyper[i];
    if (tid < NSs) inv[tid] = 1.0f / g_colsum[tid];
    if (blockIdx.x == 0)
        for (int i = tid; i < 4096; i += 256) outHy[i] = g_hyper[i];
    __syncthreads();

    int wid = tid >> 5, lane = tid & 31;
    for (int rep = 0; rep < 8; rep++) {
        int n = blockIdx.x * 64 + wid * 8 + rep;
        if (n >= Nn) break;
        int c0 = g_cls[n], c1 = g_cls[Nn + n], c2 = g_cls[2*Nn + n], c3 = g_cls[3*Nn + n];

        float v0 = inv[2*lane], v1 = inv[2*lane + 1];
#define APPLY(c, cnt) { int cc = (c); if ((cc >> 1) == lane) { \
        float ev = expf((float)(cnt)) * inv[cc]; if (cc & 1) v1 = ev; else v0 = ev; } }
        { int cnt = 1 + (c1==c0) + (c2==c0) + (c3==c0); APPLY(c0, cnt); }
        if (c1 != c0)                         { int cnt = 1 + (c2==c1) + (c3==c1); APPLY(c1, cnt); }
        if (c2 != c0 && c2 != c1)             { int cnt = 1 + (c3==c2);            APPLY(c2, cnt); }
        if (c3 != c0 && c3 != c1 && c3 != c2) {                                    APPLY(c3, 1);   }
#undef APPLY
        ((float2*)(outHs + (size_t)n*64))[lane] = make_float2(v0, v1);

        float2 v = ((const float2*)(feat + (size_t)n*64))[lane];
        frow[wid][2*lane] = v.x; frow[wid][2*lane+1] = v.y;
        __syncwarp();
        float l0 = 0.f, l1 = 0.f;
#pragma unroll
        for (int k = 0; k < 64; k += 4) {
            float4 h4 = *(const float4*)&frow[wid][k];
            float4 wa = *(const float4*)&hyT[lane][k];
            float4 wb = *(const float4*)&hyT[lane + 32][k];
            l0 += h4.x*wa.x + h4.y*wa.y + h4.z*wa.z + h4.w*wa.w;
            l1 += h4.x*wb.x + h4.y*wb.y + h4.z*wb.z + h4.w*wb.w;
        }
        const float SCALE = 0.125f;
        l0 *= SCALE; l1 *= SCALE;
#pragma unroll
        for (int rp = 0; rp < 4; rp++) {
            float* base = outD + ((size_t)rp*Nn + n)*64;
            base[lane] = l0;
            base[lane + 32] = l1;
        }
        __syncwarp();
    }
}

// ---------------- launcher ----------------
extern "C" void kernel_launch(void* const* d_in, const int* in_sizes, int n_in,
                              void* d_out, int out_size)
{
    (void)in_sizes; (void)n_in; (void)out_size;
    const int*   ei   = (const int*)d_in[0];
    const float* feat = (const float*)d_in[1];
    const float* Wlin = (const float*)d_in[2];
    const float* blin = (const float*)d_in[3];
    const float* g0W  = (const float*)d_in[4];
    const float* g0b  = (const float*)d_in[5];
    const float* g1W  = (const float*)d_in[6];
    const float* g1b  = (const float*)d_in[7];
    const float* l1W  = (const float*)d_in[8];
    const float* l1b  = (const float*)d_in[9];

    float* out   = (float*)d_out;
    float* outHs = out;
    float* outHy = out + (size_t)Nn*NSs;
    float* outD  = out + (size_t)Nn*NSs + (size_t)NSs*Ff;

    float *p_h1, *p_x2;
    cudaGetSymbolAddress((void**)&p_h1, g_h1);
    cudaGetSymbolAddress((void**)&p_x2, g_x2);

    const int GB_N = (Nn + 127) / 128;     // 391

    // per-replica linear transforms -> diff rows (+ fused global init)
    gemm_rb<<<dim3(GB_N, 3), 128>>>(feat, Wlin, blin, Nn);

    edge_kernel<<<(Ee*8)/256, 256>>>(ei, feat);
    scanAC_kernel<<<SCAN_BLOCKS, 1024>>>();
    fill_kernel<<<(Ee + 255)/256, 256>>>(ei);

    // layer 0: gather relu(feat), multiply by W0 post-aggregation
    gcn_fused<0><<<(Nn + 63)/64, 256>>>(feat, g0W, g0b, p_h1, nullptr, nullptr);

    // layer 1: gather h1, multiply by W1 post-aggregation, fused logits+argmax
    gcn_fused<1><<<(Nn + 63)/64, 256>>>(p_h1, g1W, g1b, p_x2, l1W, l1b);

    classagg_kernel<<<128, 256>>>();
    outputs_kernel<<<(Nn + 63)/64, 256>>>(feat, outHs, outHy, outD);
}

// round 16
// speedup vs baseline: 1.1827x; 1.1827x over previous
#include <cuda_runtime.h>
#include <math.h>

#define Nn 50000
#define Ee 800000
#define Ff 64
#define Tt 3
#define NSs 64
#define NTOT (4*Nn)
#define SCAN_TILE 4096
#define SCAN_BLOCKS ((Nn + SCAN_TILE - 1) / SCAN_TILE)   // 13

// ---------------- scratch (device globals; no allocation allowed) ----------------
__device__ __align__(16) float g_diff[Nn*192];   // per node: 3 normalized-difference rows
__device__ unsigned char g_mask[Ee];
__device__ unsigned long long g_pack[Nn];         // c1|c2<<16|c3<<32|deg<<48
__device__ int g_off[Nn+1];                       // after fill: g_off[i] = END of segment i
__device__ int g_eid[Ee];                         // packed: src | (mask<<16)
__device__ int g_bsum[SCAN_BLOCKS];
__device__ int g_scancnt;
__device__ float g_dinv[4*Nn];
__device__ __align__(16) float g_xw0[Nn*Ff];
__device__ __align__(16) float g_h1[NTOT*Ff];
__device__ __align__(16) float g_xw1[NTOT*Ff];
__device__ __align__(16) float g_x2[Nn*Ff];       // replica-0 rows only
__device__ int g_cls[NTOT];
__device__ __align__(16) float g_hyper[NSs*Ff];
__device__ float g_colsum[NSs];

// ---------------- register-blocked GEMM: out = (relu?)X @ W (+bias), K=N=64 ----------------
// diffMode also performs global init (g_pack/g_hyper/g_colsum/g_scancnt) in its y==0 blocks.
__global__ __launch_bounds__(128)
void gemm_rb(const float* __restrict__ X, const float* __restrict__ W,
             const float* __restrict__ bias, float* __restrict__ out,
             int rows, int relu_in, int diffMode)
{
    __shared__ float As[128*64];   // 32KB
    __shared__ float Bs[64*64];    // 16KB
    const int tid = threadIdx.x;
    const int tx = tid & 7;
    const int ty = tid >> 3;
    const int b  = blockIdx.y;
    const int row0 = blockIdx.x * 128;

    if (diffMode && b == 0) {
        int gi = blockIdx.x * 128 + tid;
        if (gi < Nn) g_pack[gi] = 0ULL;
        if (blockIdx.x == 0) {
            for (int i = tid; i < NSs*Ff; i += 128) g_hyper[i] = 0.0f;
            if (tid < NSs) g_colsum[tid] = (float)Nn;
            if (tid == 0) g_scancnt = 0;
        }
    }

    const float* Wb = W + (size_t)b * 4096;

#pragma unroll
    for (int it = 0; it < 16; it++) {
        int idx = tid + it * 128;
        int r = idx >> 4, c4 = (idx & 15) << 2;
        int gr = row0 + r;
        float4 v = make_float4(0.f, 0.f, 0.f, 0.f);
        if (gr < rows) v = *(const float4*)&X[(size_t)gr*64 + c4];
        if (relu_in) { v.x = fmaxf(v.x,0.f); v.y = fmaxf(v.y,0.f); v.z = fmaxf(v.z,0.f); v.w = fmaxf(v.w,0.f); }
        *(float4*)&As[r*64 + c4] = v;
    }
#pragma unroll
    for (int it = 0; it < 8; it++) {
        int idx = tid + it * 128;
        int k = idx >> 4, c4 = (idx & 15) << 2;
        *(float4*)&Bs[k*64 + c4] = *(const float4*)&Wb[k*64 + c4];
    }
    __syncthreads();

    float acc[8][8];
#pragma unroll
    for (int i = 0; i < 8; i++)
#pragma unroll
        for (int j = 0; j < 8; j++) acc[i][j] = 0.f;

    const int rbase = ty * 8;
    const int c0 = tx * 8;
#pragma unroll
    for (int k0 = 0; k0 < 64; k0 += 4) {
        float4 a[8];
#pragma unroll
        for (int i = 0; i < 8; i++) a[i] = *(const float4*)&As[(rbase+i)*64 + k0];
#pragma unroll
        for (int kk = 0; kk < 4; kk++) {
            float4 b0 = *(const float4*)&Bs[(k0+kk)*64 + c0];
            float4 b1 = *(const float4*)&Bs[(k0+kk)*64 + c0 + 4];
            float bb[8] = {b0.x,b0.y,b0.z,b0.w,b1.x,b1.y,b1.z,b1.w};
#pragma unroll
            for (int i = 0; i < 8; i++) {
                float av = (kk==0) ? a[i].x : (kk==1) ? a[i].y : (kk==2) ? a[i].z : a[i].w;
#pragma unroll
                for (int j = 0; j < 8; j++) acc[i][j] += av * bb[j];
            }
        }
    }

    float bj[8];
#pragma unroll
    for (int j = 0; j < 8; j++) bj[j] = bias ? bias[(size_t)b*64 + c0 + j] : 0.f;

    if (!diffMode) {
        float* outb = out + (size_t)b * rows * 64;
#pragma unroll
        for (int i = 0; i < 8; i++) {
            int gr = row0 + rbase + i;
            if (gr >= rows) continue;
            float v[8];
#pragma unroll
            for (int j = 0; j < 8; j++) v[j] = acc[i][j] + bj[j];
            *(float4*)&outb[(size_t)gr*64 + c0]     = make_float4(v[0],v[1],v[2],v[3]);
            *(float4*)&outb[(size_t)gr*64 + c0 + 4] = make_float4(v[4],v[5],v[6],v[7]);
        }
    } else {
#pragma unroll
        for (int i = 0; i < 8; i++) {
            int gr = row0 + rbase + i;
            float v[8], x[8];
            float sqv = 0.f, sqx = 0.f;
#pragma unroll
            for (int j = 0; j < 8; j++) {
                v[j] = acc[i][j] + bj[j];
                x[j] = As[(rbase+i)*64 + c0 + j];
                sqv += v[j]*v[j];
                sqx += x[j]*x[j];
            }
            sqv += __shfl_xor_sync(0xffffffffu, sqv, 1);
            sqv += __shfl_xor_sync(0xffffffffu, sqv, 2);
            sqv += __shfl_xor_sync(0xffffffffu, sqv, 4);
            sqx += __shfl_xor_sync(0xffffffffu, sqx, 1);
            sqx += __shfl_xor_sync(0xffffffffu, sqx, 2);
            sqx += __shfl_xor_sync(0xffffffffu, sqx, 4);
            float itn = 1.0f / fmaxf(sqrtf(sqv), 1e-8f);
            float ixn = 1.0f / fmaxf(sqrtf(sqx), 1e-8f);
            if (gr < rows) {
                float d[8];
#pragma unroll
                for (int j = 0; j < 8; j++) d[j] = v[j]*itn - x[j]*ixn;
                float* dst = &g_diff[(size_t)gr*192 + b*64 + c0];
                *(float4*)&dst[0] = make_float4(d[0],d[1],d[2],d[3]);
                *(float4*)&dst[4] = make_float4(d[4],d[5],d[6],d[7]);
            }
        }
    }
}

// ---------------- per-edge masks; 8 lanes per edge ----------------
__global__ void edge_kernel(const int* __restrict__ ei, const float* __restrict__ feat)
{
    int gid = blockIdx.x * blockDim.x + threadIdx.x;
    int e = gid >> 3;
    int q = threadIdx.x & 7;
    if (e >= Ee) return;
    int s = ei[e], d = ei[Ee + e];

    const float4* dp = (const float4*)(g_diff + (size_t)s*192);
    const float4* fp = (const float4*)(feat + (size_t)d*64);
    float4 f0 = fp[q],       f1 = fp[q + 8];
    float4 a0 = dp[q],       a1 = dp[q + 8];
    float4 b0 = dp[16 + q],  b1 = dp[24 + q];
    float4 c0 = dp[32 + q],  c1 = dp[40 + q];

    float p0 = a0.x*f0.x + a0.y*f0.y + a0.z*f0.z + a0.w*f0.w
             + a1.x*f1.x + a1.y*f1.y + a1.z*f1.z + a1.w*f1.w;
    float p1 = b0.x*f0.x + b0.y*f0.y + b0.z*f0.z + b0.w*f0.w
             + b1.x*f1.x + b1.y*f1.y + b1.z*f1.z + b1.w*f1.w;
    float p2 = c0.x*f0.x + c0.y*f0.y + c0.z*f0.z + c0.w*f0.w
             + c1.x*f1.x + c1.y*f1.y + c1.z*f1.z + c1.w*f1.w;
#pragma unroll
    for (int o = 4; o; o >>= 1) {
        p0 += __shfl_xor_sync(0xffffffffu, p0, o);
        p1 += __shfl_xor_sync(0xffffffffu, p1, o);
        p2 += __shfl_xor_sync(0xffffffffu, p2, o);
    }
    if (q == 0) {
        unsigned m = 0;
        unsigned long long inc = 1ULL << 48;
        if (p0 > 0.f) { m |= 1u; inc += 1ULL; }
        if (p1 > 0.f) { m |= 2u; inc += 1ULL << 16; }
        if (p2 > 0.f) { m |= 4u; inc += 1ULL << 32; }
        g_mask[e] = (unsigned char)m;
        atomicAdd(&g_pack[d], inc);
    }
}

// ---------------- single-pass scan (13 co-resident blocks, spin barrier) + dinv ----------------
__global__ void scanAC_kernel()
{
    __shared__ int wsum[32];
    __shared__ int carry_s;
    int tid = threadIdx.x, lane = tid & 31, wid = tid >> 5;
    int idx4 = blockIdx.x * SCAN_TILE + tid * 4;

    unsigned long long pk0 = 0, pk1 = 0, pk2 = 0, pk3 = 0;
    if (idx4     < Nn) pk0 = g_pack[idx4];
    if (idx4 + 1 < Nn) pk1 = g_pack[idx4+1];
    if (idx4 + 2 < Nn) pk2 = g_pack[idx4+2];
    if (idx4 + 3 < Nn) pk3 = g_pack[idx4+3];
    int v0 = (int)(pk0 >> 48), v1 = (int)(pk1 >> 48);
    int v2 = (int)(pk2 >> 48), v3 = (int)(pk3 >> 48);

    int local = v0 + v1 + v2 + v3;
    int incl = local;
#pragma unroll
    for (int o = 1; o < 32; o <<= 1) {
        int t = __shfl_up_sync(0xffffffffu, incl, o);
        if (lane >= o) incl += t;
    }
    if (lane == 31) wsum[wid] = incl;
    __syncthreads();
    if (wid == 0) {
        int s = wsum[lane];
        int si = s;
#pragma unroll
        for (int o = 1; o < 32; o <<= 1) {
            int t = __shfl_up_sync(0xffffffffu, si, o);
            if (lane >= o) si += t;
        }
        wsum[lane] = si - s;
        if (lane == 31) {
            g_bsum[blockIdx.x] = si;
            __threadfence();
            atomicAdd(&g_scancnt, 1);
        }
    }
    __syncthreads();
    int excl = wsum[wid] + (incl - local);

    if (tid == 0) {
        while (*(volatile int*)&g_scancnt < SCAN_BLOCKS) { }
        __threadfence();
        int c = 0;
        for (int j = 0; j < (int)blockIdx.x; j++) c += *(volatile int*)&g_bsum[j];
        carry_s = c;
    }
    __syncthreads();
    int carry = carry_s;
    excl += carry;

    if (idx4 + 3 < Nn) {
        *(int4*)&g_off[idx4] = make_int4(excl, excl+v0, excl+v0+v1, excl+v0+v1+v2);
    } else if (idx4 < Nn) {
        g_off[idx4] = excl;
        if (idx4+1 < Nn) g_off[idx4+1] = excl + v0;
        if (idx4+2 < Nn) g_off[idx4+2] = excl + v0 + v1;
    }
#pragma unroll
    for (int j = 0; j < 4; j++) {
        int i = idx4 + j;
        if (i >= Nn) break;
        unsigned long long pk = (j==0) ? pk0 : (j==1) ? pk1 : (j==2) ? pk2 : pk3;
        g_dinv[i]        = rsqrtf((float)(int)(pk >> 48) + 1.0f);
        g_dinv[Nn + i]   = rsqrtf((float)(int)(pk & 0xFFFF) + 2.0f);
        g_dinv[2*Nn + i] = rsqrtf((float)(int)((pk >> 16) & 0xFFFF) + 2.0f);
        g_dinv[3*Nn + i] = rsqrtf((float)(int)((pk >> 32) & 0xFFFF) + 2.0f);
    }
}

// ---------------- CSR fill: bump g_off[d] directly (after pass, g_off[i] = segment END) ----------------
__global__ void fill_kernel(const int* __restrict__ ei)
{
    int e = blockIdx.x * blockDim.x + threadIdx.x;
    if (e >= Ee) return;
    int s = ei[e];
    int d = ei[Ee + e];
    unsigned m = g_mask[e];
    int p = atomicAdd(&g_off[d], 1);
    g_eid[p] = s | ((int)m << 16);
}

// ---------------- GCN layer; FUSE=1 adds logits+argmax, 8 nodes/warp, W staged once ----------------
// Segment of node i: [ (i ? g_off[i-1] : 0), g_off[i] )   (g_off mutated by fill)
template<int FUSE>
__global__ __launch_bounds__(256)
void gcn_layer(const float* __restrict__ XW,
               const float* __restrict__ XWfull,
               const float* __restrict__ bias,
               float* __restrict__ out,
               const float* __restrict__ LW,
               const float* __restrict__ Lb)
{
    __shared__ float Wsm[FUSE ? 64*68 : 1];
    __shared__ float bs[FUSE ? 64 : 1];
    __shared__ float rowsm[FUSE ? 8 : 1][4][68];
    int tid = threadIdx.x;
    if (FUSE) {
        for (int i = tid; i < 4096; i += 256) {
            int k = i >> 6, j = i & 63;
            Wsm[k*68 + j] = LW[i];
        }
        if (tid < 64) bs[tid] = Lb[tid];
        __syncthreads();
    }

    int wid = tid >> 5;
    int lane = tid & 31;
    int h = lane >> 4;
    int q = lane & 15;

    const int NREP = FUSE ? 8 : 1;
    for (int rep = 0; rep < NREP; rep++) {
        int i = FUSE ? (blockIdx.x * 64 + wid * 8 + rep)
                     : (blockIdx.x * 8 + wid);
        if (FUSE && i >= Nn) break;

        float di0 = g_dinv[i];
        float di1 = g_dinv[Nn + i];
        float di2 = g_dinv[2*Nn + i];
        float di3 = g_dinv[3*Nn + i];
        float4 A0 = make_float4(0,0,0,0), A1 = A0, A2 = A0, A3 = A0;
        int beg = i ? g_off[i-1] : 0;
        int end = g_off[i];

#define EDGE(kk) { \
        int p = g_eid[kk]; \
        int s = p & 0xFFFF; \
        unsigned m = (unsigned)p >> 16; \
        float ad = g_dinv[s]; \
        float4 r = ((const float4*)(XW + (size_t)s*Ff))[q]; \
        float c0 = ad * di0; \
        A0.x += r.x*c0; A0.y += r.y*c0; A0.z += r.z*c0; A0.w += r.w*c0; \
        if (m & 1u) { float c = ad*di1; A1.x += r.x*c; A1.y += r.y*c; A1.z += r.z*c; A1.w += r.w*c; } \
        if (m & 2u) { float c = ad*di2; A2.x += r.x*c; A2.y += r.y*c; A2.z += r.z*c; A2.w += r.w*c; } \
        if (m & 4u) { float c = ad*di3; A3.x += r.x*c; A3.y += r.y*c; A3.z += r.z*c; A3.w += r.w*c; } }

        int k = beg + h;
        for (; k + 2 < end; k += 4) { EDGE(k); EDGE(k + 2); }
        if (k < end) EDGE(k);
#undef EDGE

#define COMB(A) \
        A.x += __shfl_xor_sync(0xffffffffu, A.x, 16); \
        A.y += __shfl_xor_sync(0xffffffffu, A.y, 16); \
        A.z += __shfl_xor_sync(0xffffffffu, A.z, 16); \
        A.w += __shfl_xor_sync(0xffffffffu, A.w, 16);
        COMB(A0) COMB(A1) COMB(A2) COMB(A3)
#undef COMB

        float4 s0 = ((const float4*)(XW + (size_t)i*Ff))[q];
        float4 bv = ((const float4*)bias)[q];

        float4 oA, oB;
        if (h == 0) {
            float c = di0*di0;
            oA.x = A0.x + s0.x*c + bv.x; oA.y = A0.y + s0.y*c + bv.y;
            oA.z = A0.z + s0.z*c + bv.z; oA.w = A0.w + s0.w*c + bv.w;
            float car = di0 * di1, cs = di1 * di1;
            float4 sr = FUSE ? ((const float4*)(XWfull + ((size_t)Nn + i)*Ff))[q] : s0;
            oB.x = A1.x + s0.x*car + sr.x*cs + bv.x; oB.y = A1.y + s0.y*car + sr.y*cs + bv.y;
            oB.z = A1.z + s0.z*car + sr.z*cs + bv.z; oB.w = A1.w + s0.w*car + sr.w*cs + bv.w;
        } else {
            float car = di0 * di2, cs = di2 * di2;
            float4 sr = FUSE ? ((const float4*)(XWfull + ((size_t)2*Nn + i)*Ff))[q] : s0;
            oA.x = A2.x + s0.x*car + sr.x*cs + bv.x; oA.y = A2.y + s0.y*car + sr.y*cs + bv.y;
            oA.z = A2.z + s0.z*car + sr.z*cs + bv.z; oA.w = A2.w + s0.w*car + sr.w*cs + bv.w;
            car = di0 * di3; cs = di3 * di3;
            sr = FUSE ? ((const float4*)(XWfull + ((size_t)3*Nn + i)*Ff))[q] : s0;
            oB.x = A3.x + s0.x*car + sr.x*cs + bv.x; oB.y = A3.y + s0.y*car + sr.y*cs + bv.y;
            oB.z = A3.z + s0.z*car + sr.z*cs + bv.z; oB.w = A3.w + s0.w*car + sr.w*cs + bv.w;
        }

        if (!FUSE) {
            float4 a = oA, b2 = oB;
            a.x=fmaxf(a.x,0.f); a.y=fmaxf(a.y,0.f); a.z=fmaxf(a.z,0.f); a.w=fmaxf(a.w,0.f);
            b2.x=fmaxf(b2.x,0.f); b2.y=fmaxf(b2.y,0.f); b2.z=fmaxf(b2.z,0.f); b2.w=fmaxf(b2.w,0.f);
            if (h == 0) {
                ((float4*)(out + (size_t)i*Ff))[q] = a;
                ((float4*)(out + ((size_t)Nn + i)*Ff))[q] = b2;
            } else {
                ((float4*)(out + ((size_t)2*Nn + i)*Ff))[q] = a;
                ((float4*)(out + ((size_t)3*Nn + i)*Ff))[q] = b2;
            }
        } else {
            if (h == 0) ((float4*)(out + (size_t)i*Ff))[q] = oA;
            *(float4*)&rowsm[wid][2*h + 0][4*q] = oA;
            *(float4*)&rowsm[wid][2*h + 1][4*q] = oB;
            __syncwarp();

            float a0[4], a1[4];
#pragma unroll
            for (int j = 0; j < 4; j++) { a0[j] = bs[4*q + j]; a1[j] = bs[4*q + j]; }
            const float* r0 = rowsm[wid][2*h + 0];
            const float* r1 = rowsm[wid][2*h + 1];
#pragma unroll 8
            for (int kk = 0; kk < 64; kk++) {
                float h0 = fmaxf(r0[kk], 0.f);
                float h1 = fmaxf(r1[kk], 0.f);
                float4 w = *(const float4*)&Wsm[kk*68 + 4*q];
                a0[0] += h0*w.x; a0[1] += h0*w.y; a0[2] += h0*w.z; a0[3] += h0*w.w;
                a1[0] += h1*w.x; a1[1] += h1*w.y; a1[2] += h1*w.z; a1[3] += h1*w.w;
            }
            float bv0 = a0[0]; int bi0 = 4*q;
            float bv1 = a1[0]; int bi1 = 4*q;
#pragma unroll
            for (int j = 1; j < 4; j++) {
                if (a0[j] > bv0) { bv0 = a0[j]; bi0 = 4*q + j; }
                if (a1[j] > bv1) { bv1 = a1[j]; bi1 = 4*q + j; }
            }
#pragma unroll
            for (int o = 1; o < 16; o <<= 1) {
                float ov0 = __shfl_xor_sync(0xffffffffu, bv0, o);
                int   oi0 = __shfl_xor_sync(0xffffffffu, bi0, o);
                float ov1 = __shfl_xor_sync(0xffffffffu, bv1, o);
                int   oi1 = __shfl_xor_sync(0xffffffffu, bi1, o);
                if (ov0 > bv0 || (ov0 == bv0 && oi0 < bi0)) { bv0 = ov0; bi0 = oi0; }
                if (ov1 > bv1 || (ov1 == bv1 && oi1 < bi1)) { bv1 = ov1; bi1 = oi1; }
            }
            if (q == 0) {
                g_cls[(size_t)(2*h + 0)*Nn + i] = bi0;
                g_cls[(size_t)(2*h + 1)*Nn + i] = bi1;
            }
            __syncwarp();
        }
    }
}

// ---------------- class aggregation: hyper + softmax column sums ----------------
__global__ void classagg_kernel()
{
    __shared__ float hy[NSs][Ff];
    __shared__ float cs[NSs];
    int tid = threadIdx.x;
    for (int i = tid; i < NSs*Ff; i += 256) (&hy[0][0])[i] = 0.0f;
    if (tid < NSs) cs[tid] = 0.0f;
    __syncthreads();
    int wid = tid >> 5, lane = tid & 31;
    for (int n = blockIdx.x * 8 + wid; n < Nn; n += gridDim.x * 8) {
        int c0 = g_cls[n], c1 = g_cls[Nn + n], c2 = g_cls[2*Nn + n], c3 = g_cls[3*Nn + n];
        float2 x = ((const float2*)(g_x2 + (size_t)n*64))[lane];
#define PROC(c, cnt) { \
        atomicAdd(&hy[(c)][2*lane], x.x); atomicAdd(&hy[(c)][2*lane+1], x.y); \
        if (lane == 0) atomicAdd(&cs[(c)], expf((float)(cnt)) - 1.0f); }
        { int cnt = 1 + (c1==c0) + (c2==c0) + (c3==c0); PROC(c0, cnt); }
        if (c1 != c0)                         { int cnt = 1 + (c2==c1) + (c3==c1); PROC(c1, cnt); }
        if (c2 != c0 && c2 != c1)             { int cnt = 1 + (c3==c2);            PROC(c2, cnt); }
        if (c3 != c0 && c3 != c1 && c3 != c2) {                                    PROC(c3, 1);   }
#undef PROC
    }
    __syncthreads();
    for (int i = tid; i < NSs*Ff; i += 256) atomicAdd(&g_hyper[i], (&hy[0][0])[i]);
    if (tid < NSs) atomicAdd(&g_colsum[tid], cs[tid]);
}

// ---------------- fused outputs: H_soft + hyper copy + dots; 8 nodes/warp ----------------
__global__ __launch_bounds__(256)
void outputs_kernel(const float* __restrict__ feat,
                    float* __restrict__ outHs, float* __restrict__ outHy,
                    float* __restrict__ outD)
{
    __shared__ __align__(16) float hyT[64][68];
    __shared__ float inv[NSs];
    __shared__ __align__(16) float frow[8][64];
    int tid = threadIdx.x;
    for (int i = tid; i < 4096; i += 256) hyT[i >> 6][i & 63] = g_hyper[i];
    if (tid < NSs) inv[tid] = 1.0f / g_colsum[tid];
    if (blockIdx.x == 0)
        for (int i = tid; i < 4096; i += 256) outHy[i] = g_hyper[i];
    __syncthreads();

    int wid = tid >> 5, lane = tid & 31;
    for (int rep = 0; rep < 8; rep++) {
        int n = blockIdx.x * 64 + wid * 8 + rep;
        if (n >= Nn) break;
        int c0 = g_cls[n], c1 = g_cls[Nn + n], c2 = g_cls[2*Nn + n], c3 = g_cls[3*Nn + n];

        float v0 = inv[2*lane], v1 = inv[2*lane + 1];
#define APPLY(c, cnt) { int cc = (c); if ((cc >> 1) == lane) { \
        float ev = expf((float)(cnt)) * inv[cc]; if (cc & 1) v1 = ev; else v0 = ev; } }
        { int cnt = 1 + (c1==c0) + (c2==c0) + (c3==c0); APPLY(c0, cnt); }
        if (c1 != c0)                         { int cnt = 1 + (c2==c1) + (c3==c1); APPLY(c1, cnt); }
        if (c2 != c0 && c2 != c1)             { int cnt = 1 + (c3==c2);            APPLY(c2, cnt); }
        if (c3 != c0 && c3 != c1 && c3 != c2) {                                    APPLY(c3, 1);   }
#undef APPLY
        ((float2*)(outHs + (size_t)n*64))[lane] = make_float2(v0, v1);

        float2 v = ((const float2*)(feat + (size_t)n*64))[lane];
        frow[wid][2*lane] = v.x; frow[wid][2*lane+1] = v.y;
        __syncwarp();
        float l0 = 0.f, l1 = 0.f;
#pragma unroll
        for (int k = 0; k < 64; k += 4) {
            float4 h4 = *(const float4*)&frow[wid][k];
            float4 wa = *(const float4*)&hyT[lane][k];
            float4 wb = *(const float4*)&hyT[lane + 32][k];
            l0 += h4.x*wa.x + h4.y*wa.y + h4.z*wa.z + h4.w*wa.w;
            l1 += h4.x*wb.x + h4.y*wb.y + h4.z*wb.z + h4.w*wb.w;
        }
        const float SCALE = 0.125f;
        l0 *= SCALE; l1 *= SCALE;
#pragma unroll
        for (int rp = 0; rp < 4; rp++) {
            float* base = outD + ((size_t)rp*Nn + n)*64;
            base[lane] = l0;
            base[lane + 32] = l1;
        }
        __syncwarp();
    }
}

// ---------------- launcher ----------------
extern "C" void kernel_launch(void* const* d_in, const int* in_sizes, int n_in,
                              void* d_out, int out_size)
{
    (void)in_sizes; (void)n_in; (void)out_size;
    const int*   ei   = (const int*)d_in[0];
    const float* feat = (const float*)d_in[1];
    const float* Wlin = (const float*)d_in[2];
    const float* blin = (const float*)d_in[3];
    const float* g0W  = (const float*)d_in[4];
    const float* g0b  = (const float*)d_in[5];
    const float* g1W  = (const float*)d_in[6];
    const float* g1b  = (const float*)d_in[7];
    const float* l1W  = (const float*)d_in[8];
    const float* l1b  = (const float*)d_in[9];

    float* out   = (float*)d_out;
    float* outHs = out;
    float* outHy = out + (size_t)Nn*NSs;
    float* outD  = out + (size_t)Nn*NSs + (size_t)NSs*Ff;

    float *p_xw0, *p_h1, *p_xw1, *p_x2;
    cudaGetSymbolAddress((void**)&p_xw0, g_xw0);
    cudaGetSymbolAddress((void**)&p_h1,  g_h1);
    cudaGetSymbolAddress((void**)&p_xw1, g_xw1);
    cudaGetSymbolAddress((void**)&p_x2,  g_x2);

    const int GB_N    = (Nn + 127) / 128;     // 391
    const int GB_NTOT = (NTOT + 127) / 128;   // 1563

    // per-replica linear transforms -> diff rows (+ fused global init)
    gemm_rb<<<dim3(GB_N, 3), 128>>>(feat, Wlin, blin, nullptr, Nn, 0, 1);

    edge_kernel<<<(Ee*8)/256, 256>>>(ei, feat);
    scanAC_kernel<<<SCAN_BLOCKS, 1024>>>();
    fill_kernel<<<(Ee + 255)/256, 256>>>(ei);

    // layer 0
    gemm_rb<<<dim3(GB_N, 1), 128>>>(feat, g0W, nullptr, p_xw0, Nn, 1, 0);
    gcn_layer<0><<<Nn/8, 256>>>(p_xw0, p_xw0, g0b, p_h1, nullptr, nullptr);

    // layer 1 (+ fused logits/argmax)
    gemm_rb<<<dim3(GB_NTOT, 1), 128>>>(p_h1, g1W, nullptr, p_xw1, NTOT, 0, 0);
    gcn_layer<1><<<(Nn + 63)/64, 256>>>(p_xw1, p_xw1, g1b, p_x2, l1W, l1b);

    classagg_kernel<<<128, 256>>>();
    outputs_kernel<<<(Nn + 63)/64, 256>>>(feat, outHs, outHy, outD);
}